// round 15
// baseline (speedup 1.0000x reference)
#include <cuda_runtime.h>
#include <cuda_fp16.h>

// 4-qubit depth-2 variational circuit, B=2^20 samples. Two kernels.
//
// Split: z_w = base_w + fp16 correction. base_w = sign_w * prod_{q in mask_w}
// cos(x_q pi) is the exact weights->0 limit (prep finds the dominant +-1
// pure-cos tensor entry per wire by integer rounding and subtracts it).
// Correction tensor T' is O(|weights|) ~ 0.02 -> fp16 Horner error ~1e-5 abs.
// main: 4 samples/thread (A,B,C,D) on wire-pair half2 lanes; all four share
// each T' load (81 LDS.64 per 4 samples); factored contraction
//   corr_w = sum_{i0} r0[i0] sum_{i1} r1[i1] sum_{i2} r2[i2] sum_{i3} r3[i3] T'.

__device__ uint2 g_T2h[81];   // .x = half2(T'_w0,T'_w1), .y = half2(T'_w2,T'_w3)
__device__ int   g_binfo[4];  // per wire: mask (bits3..0 = wires0..3) | code<<4
                              // code: 0 = none, 1 = +1, 2 = -1

__device__ __forceinline__ __half2 u2h(unsigned v) {
    return *reinterpret_cast<__half2*>(&v);
}
__device__ __forceinline__ unsigned h2u(__half2 h) {
    return *reinterpret_cast<unsigned*>(&h);
}

// ---------------- prep: shuffle-based gate evolution ----------------
__global__ void __launch_bounds__(256) qc_prep_kernel(const float* __restrict__ w) {
    __shared__ float bufR[16][16], bufI[16][16];  // [state s][column j]
    __shared__ float sA[4][16][16];
    __shared__ float2 sTrig[16];
    __shared__ float4 sT[81];
    const int tid = threadIdx.x;
    const unsigned FULL = 0xFFFFFFFFu;

    if (tid < 16) {
        float c, s;
        __sincosf(0.5f * w[tid], &s, &c);
        sTrig[tid] = make_float2(c, s);
    }
    // layout: column j = tid>>4, state s = tid&15 (pairs + perm stay in-warp)
    const int j = tid >> 4;
    const int s = tid & 15;
    const int lane = tid & 31;
    float ar = (s == j) ? 1.0f : 0.0f;
    float ai = 0.0f;
    __syncthreads();

#pragma unroll
    for (int d = 0; d < 2; ++d) {
        int src = s;
        if (src & 1) src ^= 8;
        if (src & 2) src ^= 1;
        if (src & 4) src ^= 2;
        if (src & 8) src ^= 4;
        {
            float nar = __shfl_sync(FULL, ar, (lane & 16) | src);
            float nai = __shfl_sync(FULL, ai, (lane & 16) | src);
            ar = nar; ai = nai;
        }
#pragma unroll
        for (int q = 0; q < 4; ++q) {
            const int m = 8 >> q;
            float2 ty = sTrig[d * 8 + q * 2 + 0];
            float2 tz = sTrig[d * 8 + q * 2 + 1];
            float pr = __shfl_xor_sync(FULL, ar, m);
            float pi = __shfl_xor_sync(FULL, ai, m);
            float cy = ty.x, sy = ty.y, cp = tz.x, sp = tz.y;
            float nr, ni;
            if (s & m) { nr = cy * ar + sy * pr;  ni = cy * ai + sy * pi; }
            else       { nr = cy * ar - sy * pr;  ni = cy * ai - sy * pi; }
            if (s & m) { ar = nr * cp - ni * sp;  ai = ni * cp + nr * sp; }
            else       { ar = nr * cp + ni * sp;  ai = ni * cp - nr * sp; }
        }
    }
    bufR[s][j] = ar; bufI[s][j] = ai;
    __syncthreads();

#pragma unroll
    for (int e = tid; e < 1024; e += 256) {
        int wq = e >> 8;
        int jj = (e >> 4) & 15;
        int jp = e & 15;
        int mask = 8 >> wq;
        float acc = 0.f;
#pragma unroll
        for (int ss = 0; ss < 16; ++ss) {
            float v = bufR[ss][jj] * bufR[ss][jp] + bufI[ss][jj] * bufI[ss][jp];
            acc += (ss & mask) ? -v : v;
        }
        sA[wq][jj][jp] = acc;
    }
    __syncthreads();

    if (tid < 81) {
        int k = tid / 9, l = tid % 9;
        int i0 = k / 3, i1 = k % 3, i2 = l / 3, i3 = l % 3;
        int x0 = (i0 == 2), x1 = (i1 == 2), x2 = (i2 == 2), x3 = (i3 == 2);
        int n0 = (i0 == 1), n1 = (i1 == 1), n2 = (i2 == 1), n3 = (i3 == 1);
        float t4[4] = {0.f, 0.f, 0.f, 0.f};
#pragma unroll
        for (int c = 0; c < 16; ++c) {
            int o0 = (c >> 3) & 1, o1 = (c >> 2) & 1, o2 = (c >> 1) & 1, o3 = c & 1;
            int jj = (o0 << 3) | (o1 << 2) | (o2 << 1) | o3;
            int jp = ((o0 ^ x0) << 3) | ((o1 ^ x1) << 2) | ((o2 ^ x2) << 1) | (o3 ^ x3);
            int neg = (n0 & o0) ^ (n1 & o1) ^ (n2 & o2) ^ (n3 & o3);
            float sgn = neg ? -1.0f : 1.0f;
#pragma unroll
            for (int wq = 0; wq < 4; ++wq) t4[wq] += sgn * sA[wq][jj][jp];
        }
        const float inv16 = 1.0f / 16.0f;
        sT[tid] = make_float4(t4[0] * inv16, t4[1] * inv16,
                              t4[2] * inv16, t4[3] * inv16);
    }
    __syncthreads();

    // per wire: round pure-cos entries (all indices in {0,1}) to integers;
    // record dominant (mask, sign), subtract in place.
    if (tid < 4) {
        const int wq = tid;
        int info = 0;
#pragma unroll
        for (int c = 0; c < 16; ++c) {
            int b0 = (c >> 3) & 1, b1 = (c >> 2) & 1, b2 = (c >> 1) & 1, b3 = c & 1;
            int kl = 27 * b0 + 9 * b1 + 3 * b2 + b3;
            float* p = &((float*)&sT[kl])[wq];
            float v = *p;
            float r = rintf(v);
            if (r != 0.0f) {
                *p = v - r;
                info = c | ((r > 0.0f ? 1 : 2) << 4);
            }
        }
        g_binfo[wq] = info;
    }
    __syncthreads();

    if (tid < 81) {
        float4 f = sT[tid];
        __half2 h01 = make_half2(__float2half_rn(f.x), __float2half_rn(f.y));
        __half2 h23 = make_half2(__float2half_rn(f.z), __float2half_rn(f.w));
        uint2 p; p.x = h2u(h01); p.y = h2u(h23);
        g_T2h[tid] = p;
    }
}

// base_w = sign * prod over masked wires of C[q]
__device__ __forceinline__ float base_eval(int info, const float* C) {
    int code = info >> 4;
    float b = (code == 1) ? 1.0f : ((code == 2) ? -1.0f : 0.0f);
    b *= (info & 8) ? C[0] : 1.0f;
    b *= (info & 4) ? C[1] : 1.0f;
    b *= (info & 2) ? C[2] : 1.0f;
    b *= (info & 1) ? C[3] : 1.0f;
    return b;
}

// ---------------- main: 4 samples/thread, fp16 correction + fp32 base ----------------
__global__ void __launch_bounds__(256, 2) qc_main_kernel(
    const float4* __restrict__ x, float4* __restrict__ out, int q /* B/4 */) {
    __shared__ uint2 Ts[81];
    __shared__ int sBI[4];
    int tid = threadIdx.x;
    if (tid < 81) Ts[tid] = g_T2h[tid];
    if (tid < 4) sBI[tid] = g_binfo[tid];
    __syncthreads();

    int t = blockIdx.x * 256 + tid;
    if (t >= q) return;

    const float PI_F = 3.14159265358979323846f;
    float4 xv[4];
    xv[0] = x[t];
    xv[1] = x[t + q];
    xv[2] = x[t + 2 * q];
    xv[3] = x[t + 3 * q];

    int b0 = sBI[0], b1 = sBI[1], b2 = sBI[2], b3 = sBI[3];

    __half2 C[4][4], S[4][4];     // [sample][qubit], duplicated (c,c)
    float base[4][4];             // [sample][wire] fp32 bases
#pragma unroll
    for (int smp = 0; smp < 4; ++smp) {
        float Cf[4], Sf[4];
        __sincosf(xv[smp].x * PI_F, &Sf[0], &Cf[0]);
        __sincosf(xv[smp].y * PI_F, &Sf[1], &Cf[1]);
        __sincosf(xv[smp].z * PI_F, &Sf[2], &Cf[2]);
        __sincosf(xv[smp].w * PI_F, &Sf[3], &Cf[3]);
#pragma unroll
        for (int qb = 0; qb < 4; ++qb) {
            C[smp][qb] = __float2half2_rn(Cf[qb]);
            S[smp][qb] = __float2half2_rn(Sf[qb]);
        }
        base[smp][0] = base_eval(b0, Cf);
        base[smp][1] = base_eval(b1, Cf);
        base[smp][2] = base_eval(b2, Cf);
        base[smp][3] = base_eval(b3, Cf);
    }

    // accumulators: z[sample][pair], pair0 = (w0,w1), pair1 = (w2,w3)
    __half2 z[4][2], tt[4][2], u[4][2];

#pragma unroll
    for (int i0 = 0; i0 < 3; ++i0) {
#pragma unroll
        for (int i1 = 0; i1 < 3; ++i1) {
            const int gbase = (i0 * 3 + i1) * 9;
#pragma unroll
            for (int i2 = 0; i2 < 3; ++i2) {
                uint2 a = Ts[gbase + i2 * 3 + 0];
                uint2 b = Ts[gbase + i2 * 3 + 1];
                uint2 c = Ts[gbase + i2 * 3 + 2];
                __half2 Ta0 = u2h(a.x), Ta1 = u2h(a.y);
                __half2 Tb0 = u2h(b.x), Tb1 = u2h(b.y);
                __half2 Tc0 = u2h(c.x), Tc1 = u2h(c.y);
#pragma unroll
                for (int smp = 0; smp < 4; ++smp) {
                    __half2 v0 = __hfma2(C[smp][3], Tb0, Ta0);
                    __half2 v1 = __hfma2(C[smp][3], Tb1, Ta1);
                    v0 = __hfma2(S[smp][3], Tc0, v0);
                    v1 = __hfma2(S[smp][3], Tc1, v1);
                    if (i2 == 0) { u[smp][0] = v0; u[smp][1] = v1; }
                    else if (i2 == 1) {
                        u[smp][0] = __hfma2(C[smp][2], v0, u[smp][0]);
                        u[smp][1] = __hfma2(C[smp][2], v1, u[smp][1]);
                    } else {
                        u[smp][0] = __hfma2(S[smp][2], v0, u[smp][0]);
                        u[smp][1] = __hfma2(S[smp][2], v1, u[smp][1]);
                    }
                }
            }
#pragma unroll
            for (int smp = 0; smp < 4; ++smp) {
                if (i1 == 0) { tt[smp][0] = u[smp][0]; tt[smp][1] = u[smp][1]; }
                else if (i1 == 1) {
                    tt[smp][0] = __hfma2(C[smp][1], u[smp][0], tt[smp][0]);
                    tt[smp][1] = __hfma2(C[smp][1], u[smp][1], tt[smp][1]);
                } else {
                    tt[smp][0] = __hfma2(S[smp][1], u[smp][0], tt[smp][0]);
                    tt[smp][1] = __hfma2(S[smp][1], u[smp][1], tt[smp][1]);
                }
            }
        }
#pragma unroll
        for (int smp = 0; smp < 4; ++smp) {
            if (i0 == 0) { z[smp][0] = tt[smp][0]; z[smp][1] = tt[smp][1]; }
            else if (i0 == 1) {
                z[smp][0] = __hfma2(C[smp][0], tt[smp][0], z[smp][0]);
                z[smp][1] = __hfma2(C[smp][0], tt[smp][1], z[smp][1]);
            } else {
                z[smp][0] = __hfma2(S[smp][0], tt[smp][0], z[smp][0]);
                z[smp][1] = __hfma2(S[smp][0], tt[smp][1], z[smp][1]);
            }
        }
    }

#pragma unroll
    for (int smp = 0; smp < 4; ++smp) {
        out[t + smp * q] = make_float4(
            base[smp][0] + __low2float(z[smp][0]),
            base[smp][1] + __high2float(z[smp][0]),
            base[smp][2] + __low2float(z[smp][1]),
            base[smp][3] + __high2float(z[smp][1]));
    }
}

extern "C" void kernel_launch(void* const* d_in, const int* in_sizes, int n_in,
                              void* d_out, int out_size) {
    const float* x = (const float*)d_in[0];       // [B,4]
    const float* w = (const float*)d_in[1];       // [2,4,2]
    float* out = (float*)d_out;                   // [B,4]
    int B = in_sizes[0] / 4;
    int q = B / 4;

    qc_prep_kernel<<<1, 256>>>(w);
    int blocks = (q + 255) / 256;
    qc_main_kernel<<<blocks, 256>>>((const float4*)x, (float4*)out, q);
}

// round 16
// speedup vs baseline: 1.0997x; 1.0997x over previous
#include <cuda_runtime.h>
#include <cuda_fp16.h>

// 4-qubit depth-2 variational circuit, B=2^20 samples. Two kernels.
//
// Split: z_w = base_w + fp16 correction. base_w = sign_w * prod_{q in mask_w}
// cos(x_q pi) is the exact weights->0 limit. Analytic pullback through the
// two CNOT-ring layers gives Z0->Z0Z1Z3, Z1->Z0Z2Z3, Z2->Z1Z3, Z3->Z0Z2
// (all +1): masks 13/11/5/10 in prep's encoding. Prep verifies this against
// its runtime detection; main takes a 5-mul fast path when it matches and a
// generic select-based path otherwise. Correction tensor T' is O(|weights|)
// -> fp16 Horner error ~1e-5 abs.
// main: 2 samples/thread, wire-pair half2 lanes; T' packed 32B/group so each
// group is one LDS.128 + one LDS.64.

__device__ uint4 g_Tpk[54];   // group g: [2g]={a01,a23,b01,b23} [2g+1]={c01,c23,-,-}
__device__ int   g_binfo[4];  // per wire: mask (bits3..0 = wires0..3) | code<<4
__device__ int   g_fast;      // 1 if detected base == analytic expectation

__device__ __forceinline__ __half2 u2h(unsigned v) {
    return *reinterpret_cast<__half2*>(&v);
}
__device__ __forceinline__ unsigned h2u(__half2 h) {
    return *reinterpret_cast<unsigned*>(&h);
}

// ---------------- prep: shuffle-based gate evolution ----------------
__global__ void __launch_bounds__(256) qc_prep_kernel(const float* __restrict__ w) {
    __shared__ float bufR[16][16], bufI[16][16];  // [state s][column j]
    __shared__ float sA[4][16][16];
    __shared__ float2 sTrig[16];
    __shared__ float4 sT[81];
    __shared__ uint2 sTh[81];
    const int tid = threadIdx.x;
    const unsigned FULL = 0xFFFFFFFFu;

    if (tid < 16) {
        float c, s;
        __sincosf(0.5f * w[tid], &s, &c);
        sTrig[tid] = make_float2(c, s);
    }
    // layout: column j = tid>>4, state s = tid&15 (pairs + perm stay in-warp)
    const int j = tid >> 4;
    const int s = tid & 15;
    const int lane = tid & 31;
    float ar = (s == j) ? 1.0f : 0.0f;
    float ai = 0.0f;
    __syncthreads();

#pragma unroll
    for (int d = 0; d < 2; ++d) {
        int src = s;
        if (src & 1) src ^= 8;
        if (src & 2) src ^= 1;
        if (src & 4) src ^= 2;
        if (src & 8) src ^= 4;
        {
            float nar = __shfl_sync(FULL, ar, (lane & 16) | src);
            float nai = __shfl_sync(FULL, ai, (lane & 16) | src);
            ar = nar; ai = nai;
        }
#pragma unroll
        for (int q = 0; q < 4; ++q) {
            const int m = 8 >> q;
            float2 ty = sTrig[d * 8 + q * 2 + 0];
            float2 tz = sTrig[d * 8 + q * 2 + 1];
            float pr = __shfl_xor_sync(FULL, ar, m);
            float pi = __shfl_xor_sync(FULL, ai, m);
            float cy = ty.x, sy = ty.y, cp = tz.x, sp = tz.y;
            float nr, ni;
            if (s & m) { nr = cy * ar + sy * pr;  ni = cy * ai + sy * pi; }
            else       { nr = cy * ar - sy * pr;  ni = cy * ai - sy * pi; }
            if (s & m) { ar = nr * cp - ni * sp;  ai = ni * cp + nr * sp; }
            else       { ar = nr * cp + ni * sp;  ai = ni * cp - nr * sp; }
        }
    }
    bufR[s][j] = ar; bufI[s][j] = ai;
    __syncthreads();

#pragma unroll
    for (int e = tid; e < 1024; e += 256) {
        int wq = e >> 8;
        int jj = (e >> 4) & 15;
        int jp = e & 15;
        int mask = 8 >> wq;
        float acc = 0.f;
#pragma unroll
        for (int ss = 0; ss < 16; ++ss) {
            float v = bufR[ss][jj] * bufR[ss][jp] + bufI[ss][jj] * bufI[ss][jp];
            acc += (ss & mask) ? -v : v;
        }
        sA[wq][jj][jp] = acc;
    }
    __syncthreads();

    if (tid < 81) {
        int k = tid / 9, l = tid % 9;
        int i0 = k / 3, i1 = k % 3, i2 = l / 3, i3 = l % 3;
        int x0 = (i0 == 2), x1 = (i1 == 2), x2 = (i2 == 2), x3 = (i3 == 2);
        int n0 = (i0 == 1), n1 = (i1 == 1), n2 = (i2 == 1), n3 = (i3 == 1);
        float t4[4] = {0.f, 0.f, 0.f, 0.f};
#pragma unroll
        for (int c = 0; c < 16; ++c) {
            int o0 = (c >> 3) & 1, o1 = (c >> 2) & 1, o2 = (c >> 1) & 1, o3 = c & 1;
            int jj = (o0 << 3) | (o1 << 2) | (o2 << 1) | o3;
            int jp = ((o0 ^ x0) << 3) | ((o1 ^ x1) << 2) | ((o2 ^ x2) << 1) | (o3 ^ x3);
            int neg = (n0 & o0) ^ (n1 & o1) ^ (n2 & o2) ^ (n3 & o3);
            float sgn = neg ? -1.0f : 1.0f;
#pragma unroll
            for (int wq = 0; wq < 4; ++wq) t4[wq] += sgn * sA[wq][jj][jp];
        }
        const float inv16 = 1.0f / 16.0f;
        sT[tid] = make_float4(t4[0] * inv16, t4[1] * inv16,
                              t4[2] * inv16, t4[3] * inv16);
    }
    __syncthreads();

    // per wire: round pure-cos entries (all indices in {0,1}) to integers;
    // record dominant (mask, sign), subtract in place.
    if (tid < 4) {
        const int wq = tid;
        int info = 0;
#pragma unroll
        for (int c = 0; c < 16; ++c) {
            int b0 = (c >> 3) & 1, b1 = (c >> 2) & 1, b2 = (c >> 1) & 1, b3 = c & 1;
            int kl = 27 * b0 + 9 * b1 + 3 * b2 + b3;
            float* p = &((float*)&sT[kl])[wq];
            float v = *p;
            float r = rintf(v);
            if (r != 0.0f) {
                *p = v - r;
                info = c | ((r > 0.0f ? 1 : 2) << 4);
            }
        }
        g_binfo[wq] = info;
    }
    __syncthreads();

    if (tid == 0) {
        // analytic expectation: masks 13/11/5/10, all sign=+1 (code 1)
        g_fast = (g_binfo[0] == (13 | 16) && g_binfo[1] == (11 | 16) &&
                  g_binfo[2] == (5 | 16)  && g_binfo[3] == (10 | 16)) ? 1 : 0;
    }

    if (tid < 81) {
        float4 f = sT[tid];
        __half2 h01 = make_half2(__float2half_rn(f.x), __float2half_rn(f.y));
        __half2 h23 = make_half2(__float2half_rn(f.z), __float2half_rn(f.w));
        uint2 p; p.x = h2u(h01); p.y = h2u(h23);
        sTh[tid] = p;
    }
    __syncthreads();

    // packed layout: 32B per group g = (i0*3+i1)*3+i2
    if (tid < 54) {
        int g = tid >> 1;
        uint4 v;
        if ((tid & 1) == 0) {
            uint2 a = sTh[3 * g + 0], b = sTh[3 * g + 1];
            v = make_uint4(a.x, a.y, b.x, b.y);
        } else {
            uint2 c = sTh[3 * g + 2];
            v = make_uint4(c.x, c.y, 0u, 0u);
        }
        g_Tpk[tid] = v;
    }
}

// generic base: sign * prod over masked wires of C[q]
__device__ __forceinline__ float base_eval(int info, const float* C) {
    int code = info >> 4;
    float b = (code == 1) ? 1.0f : ((code == 2) ? -1.0f : 0.0f);
    b *= (info & 8) ? C[0] : 1.0f;
    b *= (info & 4) ? C[1] : 1.0f;
    b *= (info & 2) ? C[2] : 1.0f;
    b *= (info & 1) ? C[3] : 1.0f;
    return b;
}

// ---------------- main: 2 samples/thread, fp16 correction + fp32 base ----------------
__global__ void __launch_bounds__(256) qc_main_kernel(
    const float4* __restrict__ x, float4* __restrict__ out, int h /* B/2 */) {
    __shared__ uint4 Ts4[54];
    __shared__ int sBI[4];
    __shared__ int sFast;
    int tid = threadIdx.x;
    if (tid < 54) Ts4[tid] = g_Tpk[tid];
    if (tid < 4) sBI[tid] = g_binfo[tid];
    if (tid == 4) sFast = g_fast;
    __syncthreads();

    int t = blockIdx.x * 256 + tid;
    if (t >= h) return;

    const float PI_F = 3.14159265358979323846f;
    float4 xa = x[t];
    float4 xb = x[t + h];

    float Cf[2][4], Sf[2][4];
    __sincosf(xa.x * PI_F, &Sf[0][0], &Cf[0][0]);
    __sincosf(xa.y * PI_F, &Sf[0][1], &Cf[0][1]);
    __sincosf(xa.z * PI_F, &Sf[0][2], &Cf[0][2]);
    __sincosf(xa.w * PI_F, &Sf[0][3], &Cf[0][3]);
    __sincosf(xb.x * PI_F, &Sf[1][0], &Cf[1][0]);
    __sincosf(xb.y * PI_F, &Sf[1][1], &Cf[1][1]);
    __sincosf(xb.z * PI_F, &Sf[1][2], &Cf[1][2]);
    __sincosf(xb.w * PI_F, &Sf[1][3], &Cf[1][3]);

    // fp32 bases, computed before the fp16 stream so Cf can die early
    float base[2][4];
    if (sFast) {
#pragma unroll
        for (int smp = 0; smp < 2; ++smp) {
            float p03 = Cf[smp][0] * Cf[smp][3];
            base[smp][0] = p03 * Cf[smp][1];          // Z0 -> C0 C1 C3
            base[smp][1] = p03 * Cf[smp][2];          // Z1 -> C0 C2 C3
            base[smp][2] = Cf[smp][1] * Cf[smp][3];   // Z2 -> C1 C3
            base[smp][3] = Cf[smp][0] * Cf[smp][2];   // Z3 -> C0 C2
        }
    } else {
        int b0 = sBI[0], b1 = sBI[1], b2 = sBI[2], b3 = sBI[3];
#pragma unroll
        for (int smp = 0; smp < 2; ++smp) {
            base[smp][0] = base_eval(b0, Cf[smp]);
            base[smp][1] = base_eval(b1, Cf[smp]);
            base[smp][2] = base_eval(b2, Cf[smp]);
            base[smp][3] = base_eval(b3, Cf[smp]);
        }
    }

    __half2 CA[4], SA[4], CB[4], SB[4];
#pragma unroll
    for (int qb = 0; qb < 4; ++qb) {
        CA[qb] = __float2half2_rn(Cf[0][qb]);
        SA[qb] = __float2half2_rn(Sf[0][qb]);
        CB[qb] = __float2half2_rn(Cf[1][qb]);
        SB[qb] = __float2half2_rn(Sf[1][qb]);
    }

    __half2 zA0, zA1, zB0, zB1;

#pragma unroll
    for (int i0 = 0; i0 < 3; ++i0) {
        __half2 tA0, tA1, tB0, tB1;
#pragma unroll
        for (int i1 = 0; i1 < 3; ++i1) {
            __half2 uA0, uA1, uB0, uB1;
#pragma unroll
            for (int i2 = 0; i2 < 3; ++i2) {
                const int g = (i0 * 3 + i1) * 3 + i2;
                uint4 pab = Ts4[2 * g];
                uint4 pc  = Ts4[2 * g + 1];
                __half2 Ta0 = u2h(pab.x), Ta1 = u2h(pab.y);
                __half2 Tb0 = u2h(pab.z), Tb1 = u2h(pab.w);
                __half2 Tc0 = u2h(pc.x),  Tc1 = u2h(pc.y);
                __half2 vA0 = __hfma2(CA[3], Tb0, Ta0);
                __half2 vA1 = __hfma2(CA[3], Tb1, Ta1);
                __half2 vB0 = __hfma2(CB[3], Tb0, Ta0);
                __half2 vB1 = __hfma2(CB[3], Tb1, Ta1);
                vA0 = __hfma2(SA[3], Tc0, vA0);
                vA1 = __hfma2(SA[3], Tc1, vA1);
                vB0 = __hfma2(SB[3], Tc0, vB0);
                vB1 = __hfma2(SB[3], Tc1, vB1);
                if (i2 == 0) { uA0 = vA0; uA1 = vA1; uB0 = vB0; uB1 = vB1; }
                else if (i2 == 1) {
                    uA0 = __hfma2(CA[2], vA0, uA0);
                    uA1 = __hfma2(CA[2], vA1, uA1);
                    uB0 = __hfma2(CB[2], vB0, uB0);
                    uB1 = __hfma2(CB[2], vB1, uB1);
                } else {
                    uA0 = __hfma2(SA[2], vA0, uA0);
                    uA1 = __hfma2(SA[2], vA1, uA1);
                    uB0 = __hfma2(SB[2], vB0, uB0);
                    uB1 = __hfma2(SB[2], vB1, uB1);
                }
            }
            if (i1 == 0) { tA0 = uA0; tA1 = uA1; tB0 = uB0; tB1 = uB1; }
            else if (i1 == 1) {
                tA0 = __hfma2(CA[1], uA0, tA0);
                tA1 = __hfma2(CA[1], uA1, tA1);
                tB0 = __hfma2(CB[1], uB0, tB0);
                tB1 = __hfma2(CB[1], uB1, tB1);
            } else {
                tA0 = __hfma2(SA[1], uA0, tA0);
                tA1 = __hfma2(SA[1], uA1, tA1);
                tB0 = __hfma2(SB[1], uB0, tB0);
                tB1 = __hfma2(SB[1], uB1, tB1);
            }
        }
        if (i0 == 0) { zA0 = tA0; zA1 = tA1; zB0 = tB0; zB1 = tB1; }
        else if (i0 == 1) {
            zA0 = __hfma2(CA[0], tA0, zA0);
            zA1 = __hfma2(CA[0], tA1, zA1);
            zB0 = __hfma2(CB[0], tB0, zB0);
            zB1 = __hfma2(CB[0], tB1, zB1);
        } else {
            zA0 = __hfma2(SA[0], tA0, zA0);
            zA1 = __hfma2(SA[0], tA1, zA1);
            zB0 = __hfma2(SB[0], tB0, zB0);
            zB1 = __hfma2(SB[0], tB1, zB1);
        }
    }

    out[t] = make_float4(base[0][0] + __low2float(zA0),
                         base[0][1] + __high2float(zA0),
                         base[0][2] + __low2float(zA1),
                         base[0][3] + __high2float(zA1));
    out[t + h] = make_float4(base[1][0] + __low2float(zB0),
                             base[1][1] + __high2float(zB0),
                             base[1][2] + __low2float(zB1),
                             base[1][3] + __high2float(zB1));
}

extern "C" void kernel_launch(void* const* d_in, const int* in_sizes, int n_in,
                              void* d_out, int out_size) {
    const float* x = (const float*)d_in[0];       // [B,4]
    const float* w = (const float*)d_in[1];       // [2,4,2]
    float* out = (float*)d_out;                   // [B,4]
    int B = in_sizes[0] / 4;
    int h = B / 2;

    qc_prep_kernel<<<1, 256>>>(w);
    int blocks = (h + 255) / 256;
    qc_main_kernel<<<blocks, 256>>>((const float4*)x, (float4*)out, h);
}